// round 10
// baseline (speedup 1.0000x reference)
#include <cuda_runtime.h>
#include <math.h>

// Problem shape (fixed by the dataset)
#define NROWS 262144
#define D     128
#define KCL   256

// ---------------- device scratch (no allocations allowed) ----------------
__device__ int    g_counts[KCL];
__device__ int    g_offsets[KCL + 1];
__device__ int    g_cursor[KCL];
__device__ int    g_perm[NROWS];
__device__ __align__(16) float g_centroids[KCL * D];
__device__ double g_acc[2];
__device__ int    g_is64;

__device__ __forceinline__ int load_label(const void* labels, int i, int is64) {
    if (is64) return (int)((const long long*)labels)[i];
    return ((const int*)labels)[i];
}

// ---------------- K0: init scratch + detect label dtype ----------------
__global__ void k0_init(const void* labels) {
    int t = threadIdx.x;
    if (t < KCL) g_counts[t] = 0;
    if (t == 0) {
        g_acc[0] = 0.0; g_acc[1] = 0.0;
        // Probe first 16 "elements" interpreted as int32 pairs. If labels are
        // int64 (values in [0,K)), every high word is 0. For int32 labels the
        // odd words are random labels; all-zero probability ~(1/256)^16.
        const int* p = (const int*)labels;
        int is64 = 1;
        #pragma unroll
        for (int j = 0; j < 16; j++) {
            int lo = p[2 * j], hi = p[2 * j + 1];
            if (hi != 0 || lo < 0 || lo >= KCL) is64 = 0;
        }
        g_is64 = is64;
    }
}

// ---------------- K1: per-cluster counts (smem histogram) ----------------
__global__ void k1_hist(const void* labels, int n) {
    __shared__ int h[KCL];
    for (int i = threadIdx.x; i < KCL; i += blockDim.x) h[i] = 0;
    __syncthreads();
    int is64 = g_is64;
    for (int i = blockIdx.x * blockDim.x + threadIdx.x; i < n;
         i += gridDim.x * blockDim.x)
        atomicAdd(&h[load_label(labels, i, is64)], 1);
    __syncthreads();
    for (int i = threadIdx.x; i < KCL; i += blockDim.x)
        if (h[i]) atomicAdd(&g_counts[i], h[i]);
}

// ---------------- K2: exclusive scan (K=256, trivial) ----------------
__global__ void k2_scan() {
    if (threadIdx.x == 0) {
        int s = 0;
        for (int k = 0; k < KCL; k++) {
            g_offsets[k] = s;
            g_cursor[k]  = s;
            s += g_counts[k];
        }
        g_offsets[KCL] = s;
    }
}

// ---------------- K3: scatter row indices bucketed by label ----------------
__global__ void k3_scatter(const void* labels, int n) {
    int is64 = g_is64;
    for (int i = blockIdx.x * blockDim.x + threadIdx.x; i < n;
         i += gridDim.x * blockDim.x) {
        int l = load_label(labels, i, is64);
        int p = atomicAdd(&g_cursor[l], 1);
        g_perm[p] = i;
    }
}

// ---------------- K4: per-cluster centroid (gather-sum, normalize) --------
// One block per cluster; 256 threads = 32 float4-lanes x 8 row-groups.
__global__ void k4_centroid(const float4* __restrict__ X4) {
    int k = blockIdx.x;
    int beg = g_offsets[k], end = g_offsets[k + 1];
    int lane = threadIdx.x & 31;   // float4 column within the row
    int rg   = threadIdx.x >> 5;   // row-group 0..7

    float4 acc = make_float4(0.f, 0.f, 0.f, 0.f);
    __shared__ int s_idx[256];
    for (int base = beg; base < end; base += 256) {
        int m = min(256, end - base);
        if (threadIdx.x < m) s_idx[threadIdx.x] = g_perm[base + threadIdx.x];
        __syncthreads();
        for (int j = rg; j < m; j += 8) {
            float4 v = X4[(size_t)s_idx[j] * 32 + lane];
            acc.x += v.x; acc.y += v.y; acc.z += v.z; acc.w += v.w;
        }
        __syncthreads();
    }

    __shared__ float4 sh[256];
    sh[threadIdx.x] = acc;
    __syncthreads();
    if (threadIdx.x < 32) {
        float4 s = sh[threadIdx.x];
        #pragma unroll
        for (int g = 1; g < 8; g++) {
            float4 v = sh[threadIdx.x + 32 * g];
            s.x += v.x; s.y += v.y; s.z += v.z; s.w += v.w;
        }
        int cnt = end - beg; if (cnt < 1) cnt = 1;
        float inv = 1.0f / (float)cnt;
        s.x *= inv; s.y *= inv; s.z *= inv; s.w *= inv;
        float nsq = s.x * s.x + s.y * s.y + s.z * s.z + s.w * s.w;
        #pragma unroll
        for (int sft = 16; sft > 0; sft >>= 1)
            nsq += __shfl_xor_sync(0xffffffffu, nsq, sft);
        float nrm = sqrtf(nsq);
        if (!(nrm > 0.f)) nrm = 1.f;   // empty-cluster guard (never hit)
        float4 c;
        c.x = s.x / nrm; c.y = s.y / nrm; c.z = s.z / nrm; c.w = s.w / nrm;
        ((float4*)g_centroids)[k * 32 + threadIdx.x] = c;
    }
}

// ---------------- K5: main pass — pos term + (rare) exact neg term --------
// One warp per row. Centroid table (128 KB) stays hot in L1/L2.
__global__ void k5_main(const float4* __restrict__ X4, const void* labels,
                        const float* __restrict__ hb, int n) {
    int is64 = g_is64;
    float bias = log1pf(expf(hb[0]));      // softplus(h_bias)
    float pos_bias = bias;
    float neg_bias = 9.0f * bias + 0.05f;  // GAMMA_EPS
    // Safe-skip threshold: if ||x||^2 >= thr then, with c2=1 and Cauchy-Schwarz,
    // min_neg >= x2 + 1 - 2*sqrt(x2) > neg_bias, so the neg relu is exactly 0.
    float st  = 1.0f + sqrtf(fmaxf(neg_bias, 0.f) + 1.0f) + 1.0f; // +1 margin
    float thr = st * st;

    int lane   = threadIdx.x & 31;
    int warp   = (blockIdx.x * blockDim.x + threadIdx.x) >> 5;
    int nwarps = (gridDim.x * blockDim.x) >> 5;
    const float4* C4 = (const float4*)g_centroids;

    float pos_sum = 0.f, neg_sum = 0.f;
    for (int row = warp; row < n; row += nwarps) {
        float4 xv = X4[(size_t)row * 32 + lane];
        int l = load_label(labels, row, is64);
        float4 cv = C4[l * 32 + lane];
        float x2 = xv.x * xv.x + xv.y * xv.y + xv.z * xv.z + xv.w * xv.w;
        float dp = xv.x * cv.x + xv.y * cv.y + xv.z * cv.z + xv.w * cv.w;
        #pragma unroll
        for (int s = 16; s > 0; s >>= 1) {
            x2 += __shfl_xor_sync(0xffffffffu, x2, s);
            dp += __shfl_xor_sync(0xffffffffu, dp, s);
        }
        float pv = x2 + 1.0f - 2.0f * dp - pos_bias;
        if (pv < 0.f) pv = 0.f;
        if (lane == 0) pos_sum += pv;

        if (x2 < thr) {  // warp-uniform, astronomically rare for this data
            float mn = 3.4e38f;
            for (int k = 0; k < KCL; k++) {
                if (k == l) continue;
                float4 ck = C4[k * 32 + lane];
                float dk = xv.x * ck.x + xv.y * ck.y + xv.z * ck.z + xv.w * ck.w;
                #pragma unroll
                for (int s = 16; s > 0; s >>= 1)
                    dk += __shfl_xor_sync(0xffffffffu, dk, s);
                float v = 1.0f - 2.0f * dk;
                if (v < mn) mn = v;
            }
            float nv = neg_bias - (x2 + mn);
            if (nv < 0.f) nv = 0.f;
            if (lane == 0) neg_sum += nv;
        }
    }

    __shared__ float sp[8], sn[8];
    int wid = threadIdx.x >> 5;
    if (lane == 0) { sp[wid] = pos_sum; sn[wid] = neg_sum; }
    __syncthreads();
    if (threadIdx.x == 0) {
        float tp = 0.f, tn = 0.f;
        int nw = blockDim.x >> 5;
        for (int w = 0; w < nw; w++) { tp += sp[w]; tn += sn[w]; }
        atomicAdd(&g_acc[0], (double)tp);
        atomicAdd(&g_acc[1], (double)tn);
    }
}

// ---------------- K6: finalize ----------------
__global__ void k6_final(float* out, int n) {
    if (threadIdx.x == 0) {
        out[0] = (float)(g_acc[0] / (double)n * 4.0);  // ALPHA_POS
        out[1] = (float)(g_acc[1] / (double)n * 1.0);  // ALPHA_NEG
    }
}

// ---------------- launch ----------------
extern "C" void kernel_launch(void* const* d_in, const int* in_sizes, int n_in,
                              void* d_out, int out_size) {
    const float* X      = (const float*)d_in[0];
    // d_in[1] = scores: unused by the reference math
    const void*  labels = d_in[2];
    const float* hb     = (const float*)d_in[3];
    int n = in_sizes[2];           // number of rows (labels count)

    k0_init    <<<1, 256>>>(labels);
    k1_hist    <<<512, 256>>>(labels, n);
    k2_scan    <<<1, 32>>>();
    k3_scatter <<<512, 256>>>(labels, n);
    k4_centroid<<<KCL, 256>>>((const float4*)X);
    k5_main    <<<4096, 256>>>((const float4*)X, labels, hb, n);
    k6_final   <<<1, 32>>>((float*)d_out, n);
}

// round 11
// speedup vs baseline: 1.0002x; 1.0002x over previous
#include <cuda_runtime.h>
#include <math.h>

// Problem shape (fixed by the dataset)
#define NROWS 262144
#define D     128
#define KCL   256

// ---------------- device scratch (no allocations allowed) ----------------
__device__ int    g_counts[KCL];
__device__ int    g_offsets[KCL + 1];
__device__ int    g_cursor[KCL];
__device__ int    g_perm[NROWS];
__device__ __align__(16) float g_centroids[KCL * D];
__device__ double g_acc[2];
__device__ int    g_is64;

__device__ __forceinline__ int load_label(const void* labels, int i, int is64) {
    if (is64) return (int)((const long long*)labels)[i];
    return ((const int*)labels)[i];
}

// ---------------- K0: init scratch + detect label dtype ----------------
__global__ void k0_init(const void* labels) {
    int t = threadIdx.x;
    if (t < KCL) g_counts[t] = 0;
    if (t == 0) {
        g_acc[0] = 0.0; g_acc[1] = 0.0;
        // Probe first 16 "elements" interpreted as int32 pairs. If labels are
        // int64 (values in [0,K)), every high word is 0. For int32 labels the
        // odd words are random labels; all-zero probability ~(1/256)^16.
        const int* p = (const int*)labels;
        int is64 = 1;
        #pragma unroll
        for (int j = 0; j < 16; j++) {
            int lo = p[2 * j], hi = p[2 * j + 1];
            if (hi != 0 || lo < 0 || lo >= KCL) is64 = 0;
        }
        g_is64 = is64;
    }
}

// ---------------- K1: per-cluster counts (smem histogram) ----------------
__global__ void k1_hist(const void* labels, int n) {
    __shared__ int h[KCL];
    for (int i = threadIdx.x; i < KCL; i += blockDim.x) h[i] = 0;
    __syncthreads();
    int is64 = g_is64;
    for (int i = blockIdx.x * blockDim.x + threadIdx.x; i < n;
         i += gridDim.x * blockDim.x)
        atomicAdd(&h[load_label(labels, i, is64)], 1);
    __syncthreads();
    for (int i = threadIdx.x; i < KCL; i += blockDim.x)
        if (h[i]) atomicAdd(&g_counts[i], h[i]);
}

// ---------------- K2: exclusive scan (K=256, trivial) ----------------
__global__ void k2_scan() {
    if (threadIdx.x == 0) {
        int s = 0;
        for (int k = 0; k < KCL; k++) {
            g_offsets[k] = s;
            g_cursor[k]  = s;
            s += g_counts[k];
        }
        g_offsets[KCL] = s;
    }
}

// ---------------- K3: scatter row indices bucketed by label ----------------
__global__ void k3_scatter(const void* labels, int n) {
    int is64 = g_is64;
    for (int i = blockIdx.x * blockDim.x + threadIdx.x; i < n;
         i += gridDim.x * blockDim.x) {
        int l = load_label(labels, i, is64);
        int p = atomicAdd(&g_cursor[l], 1);
        g_perm[p] = i;
    }
}

// ---------------- K4: per-cluster centroid (gather-sum, normalize) --------
// One block per cluster; 256 threads = 32 float4-lanes x 8 row-groups.
__global__ void k4_centroid(const float4* __restrict__ X4) {
    int k = blockIdx.x;
    int beg = g_offsets[k], end = g_offsets[k + 1];
    int lane = threadIdx.x & 31;   // float4 column within the row
    int rg   = threadIdx.x >> 5;   // row-group 0..7

    float4 acc = make_float4(0.f, 0.f, 0.f, 0.f);
    __shared__ int s_idx[256];
    for (int base = beg; base < end; base += 256) {
        int m = min(256, end - base);
        if (threadIdx.x < m) s_idx[threadIdx.x] = g_perm[base + threadIdx.x];
        __syncthreads();
        for (int j = rg; j < m; j += 8) {
            float4 v = X4[(size_t)s_idx[j] * 32 + lane];
            acc.x += v.x; acc.y += v.y; acc.z += v.z; acc.w += v.w;
        }
        __syncthreads();
    }

    __shared__ float4 sh[256];
    sh[threadIdx.x] = acc;
    __syncthreads();
    if (threadIdx.x < 32) {
        float4 s = sh[threadIdx.x];
        #pragma unroll
        for (int g = 1; g < 8; g++) {
            float4 v = sh[threadIdx.x + 32 * g];
            s.x += v.x; s.y += v.y; s.z += v.z; s.w += v.w;
        }
        int cnt = end - beg; if (cnt < 1) cnt = 1;
        float inv = 1.0f / (float)cnt;
        s.x *= inv; s.y *= inv; s.z *= inv; s.w *= inv;
        float nsq = s.x * s.x + s.y * s.y + s.z * s.z + s.w * s.w;
        #pragma unroll
        for (int sft = 16; sft > 0; sft >>= 1)
            nsq += __shfl_xor_sync(0xffffffffu, nsq, sft);
        float nrm = sqrtf(nsq);
        if (!(nrm > 0.f)) nrm = 1.f;   // empty-cluster guard (never hit)
        float4 c;
        c.x = s.x / nrm; c.y = s.y / nrm; c.z = s.z / nrm; c.w = s.w / nrm;
        ((float4*)g_centroids)[k * 32 + threadIdx.x] = c;
    }
}

// ---------------- K5: main pass — pos term + (rare) exact neg term --------
// One warp per row. Centroid table (128 KB) stays hot in L1/L2.
__global__ void k5_main(const float4* __restrict__ X4, const void* labels,
                        const float* __restrict__ hb, int n) {
    int is64 = g_is64;
    float bias = log1pf(expf(hb[0]));      // softplus(h_bias)
    float pos_bias = bias;
    float neg_bias = 9.0f * bias + 0.05f;  // GAMMA_EPS
    // Safe-skip threshold: if ||x||^2 >= thr then, with c2=1 and Cauchy-Schwarz,
    // min_neg >= x2 + 1 - 2*sqrt(x2) > neg_bias, so the neg relu is exactly 0.
    float st  = 1.0f + sqrtf(fmaxf(neg_bias, 0.f) + 1.0f) + 1.0f; // +1 margin
    float thr = st * st;

    int lane   = threadIdx.x & 31;
    int warp   = (blockIdx.x * blockDim.x + threadIdx.x) >> 5;
    int nwarps = (gridDim.x * blockDim.x) >> 5;
    const float4* C4 = (const float4*)g_centroids;

    float pos_sum = 0.f, neg_sum = 0.f;
    for (int row = warp; row < n; row += nwarps) {
        float4 xv = X4[(size_t)row * 32 + lane];
        int l = load_label(labels, row, is64);
        float4 cv = C4[l * 32 + lane];
        float x2 = xv.x * xv.x + xv.y * xv.y + xv.z * xv.z + xv.w * xv.w;
        float dp = xv.x * cv.x + xv.y * cv.y + xv.z * cv.z + xv.w * cv.w;
        #pragma unroll
        for (int s = 16; s > 0; s >>= 1) {
            x2 += __shfl_xor_sync(0xffffffffu, x2, s);
            dp += __shfl_xor_sync(0xffffffffu, dp, s);
        }
        float pv = x2 + 1.0f - 2.0f * dp - pos_bias;
        if (pv < 0.f) pv = 0.f;
        if (lane == 0) pos_sum += pv;

        if (x2 < thr) {  // warp-uniform, astronomically rare for this data
            float mn = 3.4e38f;
            for (int k = 0; k < KCL; k++) {
                if (k == l) continue;
                float4 ck = C4[k * 32 + lane];
                float dk = xv.x * ck.x + xv.y * ck.y + xv.z * ck.z + xv.w * ck.w;
                #pragma unroll
                for (int s = 16; s > 0; s >>= 1)
                    dk += __shfl_xor_sync(0xffffffffu, dk, s);
                float v = 1.0f - 2.0f * dk;
                if (v < mn) mn = v;
            }
            float nv = neg_bias - (x2 + mn);
            if (nv < 0.f) nv = 0.f;
            if (lane == 0) neg_sum += nv;
        }
    }

    __shared__ float sp[8], sn[8];
    int wid = threadIdx.x >> 5;
    if (lane == 0) { sp[wid] = pos_sum; sn[wid] = neg_sum; }
    __syncthreads();
    if (threadIdx.x == 0) {
        float tp = 0.f, tn = 0.f;
        int nw = blockDim.x >> 5;
        for (int w = 0; w < nw; w++) { tp += sp[w]; tn += sn[w]; }
        atomicAdd(&g_acc[0], (double)tp);
        atomicAdd(&g_acc[1], (double)tn);
    }
}

// ---------------- K6: finalize ----------------
__global__ void k6_final(float* out, int n) {
    if (threadIdx.x == 0) {
        out[0] = (float)(g_acc[0] / (double)n * 4.0);  // ALPHA_POS
        out[1] = (float)(g_acc[1] / (double)n * 1.0);  // ALPHA_NEG
    }
}

// ---------------- launch ----------------
extern "C" void kernel_launch(void* const* d_in, const int* in_sizes, int n_in,
                              void* d_out, int out_size) {
    const float* X      = (const float*)d_in[0];
    // d_in[1] = scores: unused by the reference math
    const void*  labels = d_in[2];
    const float* hb     = (const float*)d_in[3];
    int n = in_sizes[2];           // number of rows (labels count)

    k0_init    <<<1, 256>>>(labels);
    k1_hist    <<<512, 256>>>(labels, n);
    k2_scan    <<<1, 32>>>();
    k3_scatter <<<512, 256>>>(labels, n);
    k4_centroid<<<KCL, 256>>>((const float4*)X);
    k5_main    <<<4096, 256>>>((const float4*)X, labels, hb, n);
    k6_final   <<<1, 32>>>((float*)d_out, n);
}

// round 12
// speedup vs baseline: 1.0014x; 1.0012x over previous
#include <cuda_runtime.h>
#include <math.h>

// Problem shape (fixed by the dataset)
#define NROWS 262144
#define D     128
#define KCL   256

// ---------------- device scratch (no allocations allowed) ----------------
__device__ int    g_counts[KCL];
__device__ int    g_offsets[KCL + 1];
__device__ int    g_cursor[KCL];
__device__ int    g_perm[NROWS];
__device__ __align__(16) float g_centroids[KCL * D];
__device__ double g_acc[2];
__device__ int    g_is64;

__device__ __forceinline__ int load_label(const void* labels, int i, int is64) {
    if (is64) return (int)((const long long*)labels)[i];
    return ((const int*)labels)[i];
}

// ---------------- K0: init scratch + detect label dtype ----------------
__global__ void k0_init(const void* labels) {
    int t = threadIdx.x;
    if (t < KCL) g_counts[t] = 0;
    if (t == 0) {
        g_acc[0] = 0.0; g_acc[1] = 0.0;
        // Probe first 16 "elements" interpreted as int32 pairs. If labels are
        // int64 (values in [0,K)), every high word is 0. For int32 labels the
        // odd words are random labels; all-zero probability ~(1/256)^16.
        const int* p = (const int*)labels;
        int is64 = 1;
        #pragma unroll
        for (int j = 0; j < 16; j++) {
            int lo = p[2 * j], hi = p[2 * j + 1];
            if (hi != 0 || lo < 0 || lo >= KCL) is64 = 0;
        }
        g_is64 = is64;
    }
}

// ---------------- K1: per-cluster counts (smem histogram) ----------------
__global__ void k1_hist(const void* labels, int n) {
    __shared__ int h[KCL];
    for (int i = threadIdx.x; i < KCL; i += blockDim.x) h[i] = 0;
    __syncthreads();
    int is64 = g_is64;
    for (int i = blockIdx.x * blockDim.x + threadIdx.x; i < n;
         i += gridDim.x * blockDim.x)
        atomicAdd(&h[load_label(labels, i, is64)], 1);
    __syncthreads();
    for (int i = threadIdx.x; i < KCL; i += blockDim.x)
        if (h[i]) atomicAdd(&g_counts[i], h[i]);
}

// ---------------- K2: exclusive scan (K=256, trivial) ----------------
__global__ void k2_scan() {
    if (threadIdx.x == 0) {
        int s = 0;
        for (int k = 0; k < KCL; k++) {
            g_offsets[k] = s;
            g_cursor[k]  = s;
            s += g_counts[k];
        }
        g_offsets[KCL] = s;
    }
}

// ---------------- K3: scatter row indices bucketed by label ----------------
__global__ void k3_scatter(const void* labels, int n) {
    int is64 = g_is64;
    for (int i = blockIdx.x * blockDim.x + threadIdx.x; i < n;
         i += gridDim.x * blockDim.x) {
        int l = load_label(labels, i, is64);
        int p = atomicAdd(&g_cursor[l], 1);
        g_perm[p] = i;
    }
}

// ---------------- K4: per-cluster centroid (gather-sum, normalize) --------
// One block per cluster; 256 threads = 32 float4-lanes x 8 row-groups.
__global__ void k4_centroid(const float4* __restrict__ X4) {
    int k = blockIdx.x;
    int beg = g_offsets[k], end = g_offsets[k + 1];
    int lane = threadIdx.x & 31;   // float4 column within the row
    int rg   = threadIdx.x >> 5;   // row-group 0..7

    float4 acc = make_float4(0.f, 0.f, 0.f, 0.f);
    __shared__ int s_idx[256];
    for (int base = beg; base < end; base += 256) {
        int m = min(256, end - base);
        if (threadIdx.x < m) s_idx[threadIdx.x] = g_perm[base + threadIdx.x];
        __syncthreads();
        for (int j = rg; j < m; j += 8) {
            float4 v = X4[(size_t)s_idx[j] * 32 + lane];
            acc.x += v.x; acc.y += v.y; acc.z += v.z; acc.w += v.w;
        }
        __syncthreads();
    }

    __shared__ float4 sh[256];
    sh[threadIdx.x] = acc;
    __syncthreads();
    if (threadIdx.x < 32) {
        float4 s = sh[threadIdx.x];
        #pragma unroll
        for (int g = 1; g < 8; g++) {
            float4 v = sh[threadIdx.x + 32 * g];
            s.x += v.x; s.y += v.y; s.z += v.z; s.w += v.w;
        }
        int cnt = end - beg; if (cnt < 1) cnt = 1;
        float inv = 1.0f / (float)cnt;
        s.x *= inv; s.y *= inv; s.z *= inv; s.w *= inv;
        float nsq = s.x * s.x + s.y * s.y + s.z * s.z + s.w * s.w;
        #pragma unroll
        for (int sft = 16; sft > 0; sft >>= 1)
            nsq += __shfl_xor_sync(0xffffffffu, nsq, sft);
        float nrm = sqrtf(nsq);
        if (!(nrm > 0.f)) nrm = 1.f;   // empty-cluster guard (never hit)
        float4 c;
        c.x = s.x / nrm; c.y = s.y / nrm; c.z = s.z / nrm; c.w = s.w / nrm;
        ((float4*)g_centroids)[k * 32 + threadIdx.x] = c;
    }
}

// ---------------- K5: main pass — pos term + (rare) exact neg term --------
// One warp per row. Centroid table (128 KB) stays hot in L1/L2.
__global__ void k5_main(const float4* __restrict__ X4, const void* labels,
                        const float* __restrict__ hb, int n) {
    int is64 = g_is64;
    float bias = log1pf(expf(hb[0]));      // softplus(h_bias)
    float pos_bias = bias;
    float neg_bias = 9.0f * bias + 0.05f;  // GAMMA_EPS
    // Safe-skip threshold: if ||x||^2 >= thr then, with c2=1 and Cauchy-Schwarz,
    // min_neg >= x2 + 1 - 2*sqrt(x2) > neg_bias, so the neg relu is exactly 0.
    float st  = 1.0f + sqrtf(fmaxf(neg_bias, 0.f) + 1.0f) + 1.0f; // +1 margin
    float thr = st * st;

    int lane   = threadIdx.x & 31;
    int warp   = (blockIdx.x * blockDim.x + threadIdx.x) >> 5;
    int nwarps = (gridDim.x * blockDim.x) >> 5;
    const float4* C4 = (const float4*)g_centroids;

    float pos_sum = 0.f, neg_sum = 0.f;
    for (int row = warp; row < n; row += nwarps) {
        float4 xv = X4[(size_t)row * 32 + lane];
        int l = load_label(labels, row, is64);
        float4 cv = C4[l * 32 + lane];
        float x2 = xv.x * xv.x + xv.y * xv.y + xv.z * xv.z + xv.w * xv.w;
        float dp = xv.x * cv.x + xv.y * cv.y + xv.z * cv.z + xv.w * cv.w;
        #pragma unroll
        for (int s = 16; s > 0; s >>= 1) {
            x2 += __shfl_xor_sync(0xffffffffu, x2, s);
            dp += __shfl_xor_sync(0xffffffffu, dp, s);
        }
        float pv = x2 + 1.0f - 2.0f * dp - pos_bias;
        if (pv < 0.f) pv = 0.f;
        if (lane == 0) pos_sum += pv;

        if (x2 < thr) {  // warp-uniform, astronomically rare for this data
            float mn = 3.4e38f;
            for (int k = 0; k < KCL; k++) {
                if (k == l) continue;
                float4 ck = C4[k * 32 + lane];
                float dk = xv.x * ck.x + xv.y * ck.y + xv.z * ck.z + xv.w * ck.w;
                #pragma unroll
                for (int s = 16; s > 0; s >>= 1)
                    dk += __shfl_xor_sync(0xffffffffu, dk, s);
                float v = 1.0f - 2.0f * dk;
                if (v < mn) mn = v;
            }
            float nv = neg_bias - (x2 + mn);
            if (nv < 0.f) nv = 0.f;
            if (lane == 0) neg_sum += nv;
        }
    }

    __shared__ float sp[8], sn[8];
    int wid = threadIdx.x >> 5;
    if (lane == 0) { sp[wid] = pos_sum; sn[wid] = neg_sum; }
    __syncthreads();
    if (threadIdx.x == 0) {
        float tp = 0.f, tn = 0.f;
        int nw = blockDim.x >> 5;
        for (int w = 0; w < nw; w++) { tp += sp[w]; tn += sn[w]; }
        atomicAdd(&g_acc[0], (double)tp);
        atomicAdd(&g_acc[1], (double)tn);
    }
}

// ---------------- K6: finalize ----------------
__global__ void k6_final(float* out, int n) {
    if (threadIdx.x == 0) {
        out[0] = (float)(g_acc[0] / (double)n * 4.0);  // ALPHA_POS
        out[1] = (float)(g_acc[1] / (double)n * 1.0);  // ALPHA_NEG
    }
}

// ---------------- launch ----------------
extern "C" void kernel_launch(void* const* d_in, const int* in_sizes, int n_in,
                              void* d_out, int out_size) {
    const float* X      = (const float*)d_in[0];
    // d_in[1] = scores: unused by the reference math
    const void*  labels = d_in[2];
    const float* hb     = (const float*)d_in[3];
    int n = in_sizes[2];           // number of rows (labels count)

    k0_init    <<<1, 256>>>(labels);
    k1_hist    <<<512, 256>>>(labels, n);
    k2_scan    <<<1, 32>>>();
    k3_scatter <<<512, 256>>>(labels, n);
    k4_centroid<<<KCL, 256>>>((const float4*)X);
    k5_main    <<<4096, 256>>>((const float4*)X, labels, hb, n);
    k6_final   <<<1, 32>>>((float*)d_out, n);
}